// round 7
// baseline (speedup 1.0000x reference)
#include <cuda_runtime.h>
#include <cuda_bf16.h>
#include <cstdint>

#define TOKENS 16384
#define DIMSZ  4096
#define RNK    128

// ---------------- device scratch ----------------
__device__ __nv_bfloat16 g_Wd_hi[RNK * DIMSZ];
__device__ __nv_bfloat16 g_Wd_lo[RNK * DIMSZ];
__device__ __nv_bfloat16 g_Wu_hi[DIMSZ * RNK];
__device__ __nv_bfloat16 g_Wu_lo[DIMSZ * RNK];
__device__ __nv_bfloat16 g_H_hi [TOKENS * RNK];
__device__ __nv_bfloat16 g_H_lo [TOKENS * RNK];
__device__ float         g_r    [TOKENS];

// ---------------- helpers ----------------
__device__ __forceinline__ uint32_t smem_u32(const void* p) {
    uint32_t a;
    asm("{ .reg .u64 t; cvta.to.shared.u64 t, %1; cvt.u32.u64 %0, t; }" : "=r"(a) : "l"(p));
    return a;
}
#define SWZ(b) ((b) ^ (((b) >> 3) & 0x70))

#define CP_ASYNC16(dst, src) \
    asm volatile("cp.async.cg.shared.global [%0], [%1], 16;" :: "r"(dst), "l"(src))
#define CP_COMMIT() asm volatile("cp.async.commit_group;" ::: "memory")
#define CP_WAIT0()  asm volatile("cp.async.wait_group 0;" ::: "memory")

__device__ __forceinline__ void ldm4(uint32_t* r, uint32_t addr) {
    asm volatile("ldmatrix.sync.aligned.m8n8.x4.shared.b16 {%0,%1,%2,%3}, [%4];"
                 : "=r"(r[0]), "=r"(r[1]), "=r"(r[2]), "=r"(r[3]) : "r"(addr));
}
__device__ __forceinline__ void mma_bf16(float* d, const uint32_t* a, uint32_t b0, uint32_t b1) {
    asm volatile("mma.sync.aligned.m16n8k16.row.col.f32.bf16.bf16.f32 "
                 "{%0,%1,%2,%3}, {%4,%5,%6,%7}, {%8,%9}, {%0,%1,%2,%3};"
                 : "+f"(d[0]), "+f"(d[1]), "+f"(d[2]), "+f"(d[3])
                 : "r"(a[0]), "r"(a[1]), "r"(a[2]), "r"(a[3]), "r"(b0), "r"(b1));
}

__device__ __forceinline__ void bfsplit(float v, uint16_t& h, uint16_t& l) {
    __nv_bfloat16 bh = __float2bfloat16(v);
    float r = v - __bfloat162float(bh);
    __nv_bfloat16 bl = __float2bfloat16(r);
    h = __bfloat16_as_ushort(bh);
    l = __bfloat16_as_ushort(bl);
}

// ---------------- kernel 0: split weights into hi/lo planes ----------------
__global__ void kprep(const float* __restrict__ Wd, const float* __restrict__ Wu) {
    int i = blockIdx.x * blockDim.x + threadIdx.x;
    uint16_t h, l;
    if (i < RNK * DIMSZ) {
        bfsplit(Wd[i], h, l);
        g_Wd_hi[i] = __ushort_as_bfloat16(h);
        g_Wd_lo[i] = __ushort_as_bfloat16(l);
    } else {
        int j = i - RNK * DIMSZ;
        bfsplit(Wu[j], h, l);
        g_Wu_hi[j] = __ushort_as_bfloat16(h);
        g_Wu_lo[j] = __ushort_as_bfloat16(l);
    }
}

// ---------------- kernel 1 ----------------
// C[16384,128] = X @ Wd^T with fused sumsq; epilogue silu -> H planes + g_r.
// CTA: M=128 tokens, N=128, K chunks of 64, double-buffered.
// smem/buf (64KB): XH 16K | XL 16K | WH 16K | WL 16K. 2 bufs + small.
static constexpr int SMEM1 = 1024 + 2 * 65536 + 1024;

__global__ __launch_bounds__(256, 1) void k1_rms_gemm(const float* __restrict__ x) {
    extern __shared__ char smem_raw[];
    uint32_t sb = smem_u32(smem_raw);
    uint32_t al = (sb + 1023u) & ~1023u;
    char* sal = smem_raw + (al - sb);

    const uint32_t OFF_SS = 2 * 65536;       // 128 f32 sumsq
    const uint32_t OFF_RV = OFF_SS + 512;    // 128 f32 rv

    int tid = threadIdx.x;
    int wid = tid >> 5;
    int l   = tid & 31;
    int m0  = blockIdx.x * 128;

    if (tid < 128) ((float*)(sal + OFF_SS))[tid] = 0.f;

    // X loader mapping: rows it*16 + rsub, 16 float4-cols
    int rsub = tid >> 4;
    int col4 = tid & 15;

    float4 xr[8];
    float  ssp[8];
#pragma unroll
    for (int i = 0; i < 8; i++) ssp[i] = 0.f;

    auto loadX = [&](int c) {
        int k0 = c * 64;
#pragma unroll
        for (int it = 0; it < 8; it++) {
            int row = it * 16 + rsub;
            xr[it] = *(const float4*)(x + (size_t)(m0 + row) * DIMSZ + k0 + col4 * 4);
        }
    };
    auto storeX = [&](int buf) {
        uint32_t bufb = (uint32_t)buf * 65536u;
#pragma unroll
        for (int it = 0; it < 8; it++) {
            int row = it * 16 + rsub;
            float4 v = xr[it];
            ssp[it] += v.x * v.x + v.y * v.y + v.z * v.z + v.w * v.w;
            uint16_t h0, l0, h1, l1, h2, l2, h3, l3;
            bfsplit(v.x, h0, l0); bfsplit(v.y, h1, l1);
            bfsplit(v.z, h2, l2); bfsplit(v.w, h3, l3);
            uint2 hp, lp;
            hp.x = (uint32_t)h0 | ((uint32_t)h1 << 16);
            hp.y = (uint32_t)h2 | ((uint32_t)h3 << 16);
            lp.x = (uint32_t)l0 | ((uint32_t)l1 << 16);
            lp.y = (uint32_t)l2 | ((uint32_t)l3 << 16);
            uint32_t so = SWZ((uint32_t)row * 128 + (uint32_t)col4 * 8);
            *(uint2*)(sal + bufb + so) = hp;            // XH
            *(uint2*)(sal + bufb + 16384 + so) = lp;    // XL
        }
    };
    auto loadW = [&](int c, int buf) {
        uint32_t bufb = (uint32_t)buf * 65536u;
        int k0 = c * 64;
#pragma unroll
        for (int i = 0; i < 8; i++) {
            int idx = tid + i * 256;             // 0..2047
            int plane = idx >> 10;               // 0=hi,1=lo
            int rem = idx & 1023;
            int row = rem >> 3;
            int ci  = rem & 7;
            const char* src = (const char*)(plane ? g_Wd_lo : g_Wd_hi)
                              + (size_t)row * (DIMSZ * 2) + (size_t)k0 * 2 + ci * 16;
            uint32_t dst = al + bufb + 32768 + (uint32_t)plane * 16384
                           + SWZ((uint32_t)row * 128 + (uint32_t)ci * 16);
            CP_ASYNC16(dst, src);
        }
    };

    // warp tiles: 4 (M) x 2 (N) grid; warp tile 32x64
    int wm0 = (wid & 3) * 32;
    int wn0 = (wid >> 2) * 64;

    // lane addressing for ldmatrix
    uint32_t a_row = (uint32_t)(l & 15);
    uint32_t a_kb  = (uint32_t)((l >> 4) * 16);
    uint32_t lx    = (uint32_t)((l & 7) * 16);
    uint32_t b_row = (uint32_t)((l >> 4) * 8 + (l & 7));
    uint32_t b_kb  = (uint32_t)(((l >> 3) & 1) * 16);

    float acc[2][8][4];
#pragma unroll
    for (int mt = 0; mt < 2; mt++)
#pragma unroll
        for (int nt = 0; nt < 8; nt++)
#pragma unroll
            for (int j = 0; j < 4; j++) acc[mt][nt][j] = 0.f;

    // prologue
    loadX(0);
    storeX(0);
    loadW(0, 0);
    CP_COMMIT();
    loadX(1);

    for (int c = 0; c < 64; c++) {
        int buf = c & 1;
        CP_WAIT0();
        __syncthreads();
        if (c < 63) {
            loadW(c + 1, buf ^ 1);
            CP_COMMIT();
            storeX(buf ^ 1);
        }
        if (c < 62) loadX(c + 2);

        uint32_t bufb = al + (uint32_t)buf * 65536u;
#pragma unroll
        for (int ks = 0; ks < 4; ks++) {
            uint32_t kso = (uint32_t)ks * 32;
            uint32_t ah[2][4], alo[2][4];
#pragma unroll
            for (int mt = 0; mt < 2; mt++) {
                uint32_t ro = ((uint32_t)(wm0 + mt * 16) + a_row) * 128;
                uint32_t ko = (kso + a_kb) ^ lx;
                ldm4(ah[mt],  bufb + ro + ko);
                ldm4(alo[mt], bufb + 16384 + ro + ko);
            }
            uint32_t bh[4][4], bl[4][4];
#pragma unroll
            for (int pr = 0; pr < 4; pr++) {
                uint32_t ro = ((uint32_t)(wn0 + pr * 16) + b_row) * 128;
                uint32_t ko = (kso + b_kb) ^ lx;
                ldm4(bh[pr], bufb + 32768 + ro + ko);
                ldm4(bl[pr], bufb + 49152 + ro + ko);
            }
#pragma unroll
            for (int mt = 0; mt < 2; mt++)
#pragma unroll
                for (int nt = 0; nt < 8; nt++) {
                    int pr = nt >> 1, of = (nt & 1) * 2;
                    mma_bf16(acc[mt][nt], ah[mt],  bh[pr][of], bh[pr][of + 1]);
                    mma_bf16(acc[mt][nt], ah[mt],  bl[pr][of], bl[pr][of + 1]);
                    mma_bf16(acc[mt][nt], alo[mt], bh[pr][of], bh[pr][of + 1]);
                }
        }
    }

    // ---- sumsq reduce -> rv ----
#pragma unroll
    for (int it = 0; it < 8; it++)
        atomicAdd(((float*)(sal + OFF_SS)) + it * 16 + rsub, ssp[it]);
    __syncthreads();
    if (tid < 128) {
        float rv = rsqrtf(((float*)(sal + OFF_SS))[tid] * (1.0f / 4096.0f) + 1.1920929e-7f);
        ((float*)(sal + OFF_RV))[tid] = rv;
        g_r[m0 + tid] = rv;
    }
    __syncthreads();

    // ---- epilogue: h = silu(rv*acc), split, store planes ----
    const float* RV = (const float*)(sal + OFF_RV);
#pragma unroll
    for (int mt = 0; mt < 2; mt++) {
#pragma unroll
        for (int rh = 0; rh < 2; rh++) {
            int row = wm0 + mt * 16 + rh * 8 + (l >> 2);
            float rv = RV[row];
#pragma unroll
            for (int nt = 0; nt < 8; nt++) {
                int col = wn0 + nt * 8 + 2 * (l & 3);
                float z0 = acc[mt][nt][rh * 2 + 0] * rv;
                float z1 = acc[mt][nt][rh * 2 + 1] * rv;
                float h0 = z0 / (1.0f + __expf(-z0));
                float h1 = z1 / (1.0f + __expf(-z1));
                uint16_t a0, b0, a1, b1;
                bfsplit(h0, a0, b0);
                bfsplit(h1, a1, b1);
                size_t o = (size_t)(m0 + row) * RNK + col;
                *(uint32_t*)((char*)g_H_hi + o * 2) = (uint32_t)a0 | ((uint32_t)a1 << 16);
                *(uint32_t*)((char*)g_H_lo + o * 2) = (uint32_t)b0 | ((uint32_t)b1 << 16);
            }
        }
    }
}

// ---------------- kernel 2 ----------------
// out = x * r * sigmoid(H @ Wu^T). CTA: M=128 tokens x N=128 dims, K=128.
// smem: AH 32K | AL 32K | BH 32K | BL 32K = 128KB (+small). Planes laid out as
// [kchunk(2)][row(128)][128B].
static constexpr int SMEM2 = 1024 + 131072 + 1024;

__global__ __launch_bounds__(256, 1) void k2_gate(const float* __restrict__ x,
                                                  float* __restrict__ out) {
    extern __shared__ char smem_raw[];
    uint32_t sb = smem_u32(smem_raw);
    uint32_t al = (sb + 1023u) & ~1023u;
    char* sal = smem_raw + (al - sb);
    const uint32_t OFF_RV = 131072;

    int tid = threadIdx.x;
    int wid = tid >> 5;
    int l   = tid & 31;
    int m0  = blockIdx.y * 128;
    int d0  = blockIdx.x * 128;

    // issue all cp.asyncs: 8192 16B chunks, 32/thread
#pragma unroll
    for (int i = 0; i < 32; i++) {
        int idx = tid + i * 256;
        int operand = idx >> 12;          // 0=A(H), 1=B(Wu)
        int plane = (idx >> 11) & 1;      // 0=hi,1=lo
        int rem = idx & 2047;
        int row = rem >> 4;
        int ci  = rem & 15;
        const char* base;
        size_t srow;
        if (operand == 0) {
            base = (const char*)(plane ? g_H_lo : g_H_hi);
            srow = (size_t)(m0 + row);
        } else {
            base = (const char*)(plane ? g_Wu_lo : g_Wu_hi);
            srow = (size_t)(d0 + row);
        }
        const char* src = base + srow * 256 + ci * 16;
        uint32_t dst = al + (uint32_t)operand * 65536 + (uint32_t)plane * 32768
                       + (uint32_t)(ci >> 3) * 16384
                       + SWZ((uint32_t)row * 128 + (uint32_t)(ci & 7) * 16);
        CP_ASYNC16(dst, src);
    }
    CP_COMMIT();

    if (tid < 128) ((float*)(sal + OFF_RV))[tid] = g_r[m0 + tid];

    // warp tiles: 2(M) x 4(N); warp tile 64x32
    int wm0 = (wid & 1) * 64;
    int wn0 = (wid >> 1) * 32;

    uint32_t a_row = (uint32_t)(l & 15);
    uint32_t a_kb  = (uint32_t)((l >> 4) * 16);
    uint32_t lx    = (uint32_t)((l & 7) * 16);
    uint32_t b_row = (uint32_t)((l >> 4) * 8 + (l & 7));
    uint32_t b_kb  = (uint32_t)(((l >> 3) & 1) * 16);

    float acc[4][4][4];
#pragma unroll
    for (int mt = 0; mt < 4; mt++)
#pragma unroll
        for (int nt = 0; nt < 4; nt++)
#pragma unroll
            for (int j = 0; j < 4; j++) acc[mt][nt][j] = 0.f;

    CP_WAIT0();
    __syncthreads();

#pragma unroll
    for (int ks = 0; ks < 8; ks++) {
        uint32_t kso = (uint32_t)ks * 32;
        uint32_t ah[4][4], alo[4][4];
#pragma unroll
        for (int mt = 0; mt < 4; mt++) {
            uint32_t kt = kso + a_kb;
            uint32_t co = (kt >> 7) * 16384;
            uint32_t ro = ((uint32_t)(wm0 + mt * 16) + a_row) * 128;
            uint32_t ko = ((kt & 127) ^ lx);
            ldm4(ah[mt],  al + co + ro + ko);
            ldm4(alo[mt], al + 32768 + co + ro + ko);
        }
        uint32_t bh[2][4], bl[2][4];
#pragma unroll
        for (int pr = 0; pr < 2; pr++) {
            uint32_t kt = kso + b_kb;
            uint32_t co = (kt >> 7) * 16384;
            uint32_t ro = ((uint32_t)(wn0 + pr * 16) + b_row) * 128;
            uint32_t ko = ((kt & 127) ^ lx);
            ldm4(bh[pr], al + 65536 + co + ro + ko);
            ldm4(bl[pr], al + 98304 + co + ro + ko);
        }
#pragma unroll
        for (int mt = 0; mt < 4; mt++)
#pragma unroll
            for (int nt = 0; nt < 4; nt++) {
                int pr = nt >> 1, of = (nt & 1) * 2;
                mma_bf16(acc[mt][nt], ah[mt],  bh[pr][of], bh[pr][of + 1]);
                mma_bf16(acc[mt][nt], ah[mt],  bl[pr][of], bl[pr][of + 1]);
                mma_bf16(acc[mt][nt], alo[mt], bh[pr][of], bh[pr][of + 1]);
            }
    }

    // ---- epilogue: out = x * rv * sigmoid(acc) ----
    const float* RV = (const float*)(sal + OFF_RV);
#pragma unroll
    for (int mt = 0; mt < 4; mt++) {
#pragma unroll
        for (int rh = 0; rh < 2; rh++) {
            int row = wm0 + mt * 16 + rh * 8 + (l >> 2);
            float rv = RV[row];
#pragma unroll
            for (int nt = 0; nt < 4; nt++) {
                int col = d0 + wn0 + nt * 8 + 2 * (l & 3);
                float z0 = acc[mt][nt][rh * 2 + 0];
                float z1 = acc[mt][nt][rh * 2 + 1];
                float g0 = 1.0f / (1.0f + __expf(-z0));
                float g1 = 1.0f / (1.0f + __expf(-z1));
                size_t o = (size_t)(m0 + row) * DIMSZ + col;
                float2 xv = *(const float2*)(x + o);
                float2 ov;
                ov.x = xv.x * rv * g0;
                ov.y = xv.y * rv * g1;
                *(float2*)(out + o) = ov;
            }
        }
    }
}

// ---------------- launch ----------------
extern "C" void kernel_launch(void* const* d_in, const int* in_sizes, int n_in,
                              void* d_out, int out_size) {
    const float* x  = (const float*)d_in[0];
    const float* Wd = (const float*)d_in[1];
    const float* Wu = (const float*)d_in[2];
    float* out = (float*)d_out;

    cudaFuncSetAttribute(k1_rms_gemm, cudaFuncAttributeMaxDynamicSharedMemorySize, SMEM1);
    cudaFuncSetAttribute(k2_gate,     cudaFuncAttributeMaxDynamicSharedMemorySize, SMEM2);

    kprep<<<(2 * RNK * DIMSZ) / 256, 256>>>(Wd, Wu);
    k1_rms_gemm<<<TOKENS / 128, 256, SMEM1>>>(x);
    k2_gate<<<dim3(DIMSZ / 128, TOKENS / 128), 256, SMEM2>>>(x, out);
}